// round 4
// baseline (speedup 1.0000x reference)
#include <cuda_runtime.h>

// out[oc,h,w] = sum_{k,ic} w[oc,k,ic] * xr[ic, (h-1)%14, w+k-1]   (zero pad on w+k-1)
// xr[ic,hh,j] = x[ic,hh,(j-1)%14] (W-roll); output H-roll folded into reading
// x row (h-1)%14 for output row h.
//
// Warp-per-(oc,h): grid = 112 CTAs x 128 threads (4 warps). Each lane covers
// 4 input channels; warp butterfly reduce; no smem, no __syncthreads.

__global__ __launch_bounds__(128, 8)
void rolled_conv_kernel(const float* __restrict__ x,
                        const float* __restrict__ w,
                        float* __restrict__ out) {
    const int warp = threadIdx.x >> 5;
    const int lane = threadIdx.x & 31;
    const int pair = blockIdx.x * 4 + warp;   // 0..447 = oc*14 + h
    const int oc = pair / 14;
    const int h  = pair - oc * 14;
    const int hm1 = (h + 13) % 14;            // x row feeding this output row

    float acc[14];
#pragma unroll
    for (int wi = 0; wi < 14; wi++) acc[wi] = 0.0f;

#pragma unroll
    for (int c = 0; c < 4; c++) {
        const int ic = lane + 32 * c;

        // x row: 14 floats; offset ic*196 + hm1*14 is even -> 7x LDG.64
        const float2* xr2 = reinterpret_cast<const float2*>(x + ic * 196 + hm1 * 14);
        float xrow[14];
#pragma unroll
        for (int j = 0; j < 7; j++) {
            float2 v = __ldg(xr2 + j);
            xrow[2 * j]     = v.x;
            xrow[2 * j + 1] = v.y;
        }

        // w[oc][k][ic]: contiguous in ic -> each LDG fully coalesced per warp
        const float w0 = __ldg(w + oc * 384 + 0 * 128 + ic);
        const float w1 = __ldg(w + oc * 384 + 1 * 128 + ic);
        const float w2 = __ldg(w + oc * 384 + 2 * 128 + ic);

#pragma unroll
        for (int wi = 0; wi < 14; wi++) {
            float a = acc[wi];
            a += w1 * xrow[(wi + 13) % 14];            // k=1 (always valid)
            if (wi >= 1)  a += w0 * xrow[(wi + 12) % 14]; // k=0
            if (wi <= 12) a += w2 * xrow[wi];             // k=2
            acc[wi] = a;
        }
    }

    // Warp butterfly: all lanes end with the full 128-channel sums
#pragma unroll
    for (int off = 16; off > 0; off >>= 1) {
#pragma unroll
        for (int wi = 0; wi < 14; wi++)
            acc[wi] += __shfl_xor_sync(0xffffffffu, acc[wi], off);
    }

    if (lane < 14)
        out[oc * 196 + h * 14 + lane] = acc[lane];
}

extern "C" void kernel_launch(void* const* d_in, const int* in_sizes, int n_in,
                              void* d_out, int out_size) {
    const float* x = (const float*)d_in[0];   // (1,128,14,14) = 25088 floats
    const float* w = (const float*)d_in[1];   // (32,3,128)    = 12288 floats
    float* out = (float*)d_out;               // (1,32,14,14)  = 6272 floats

    rolled_conv_kernel<<<112, 128>>>(x, w, out);
}

// round 5
// speedup vs baseline: 1.0335x; 1.0335x over previous
#include <cuda_runtime.h>

// out[oc,h,w] = sum_{k,ic} w[oc,k,ic] * xr[ic, (h-1)%14, w+k-1]  (zero pad on w+k-1)
// xr[ic,hh,j] = x[ic,hh,(j-1)%14] (W-roll); output H-roll folded into reading
// x row (h-1)%14 for output row h.
//
// Grid (14 h, 32 oc) x 256 threads: ic = tid&127, colgrp = tid>>7 (7 columns each).
// Reduction: two-stage smem tree.

__global__ __launch_bounds__(256, 4)
void rolled_conv_kernel(const float* __restrict__ x,
                        const float* __restrict__ w,
                        float* __restrict__ out) {
    __shared__ float part[128][16];   // cols 0-6 = colgrp0 (wi 0-6), cols 8-14 = colgrp1 (wi 7-13)
    __shared__ float part2[8][14];

    const int h  = blockIdx.x;          // output row 0..13
    const int oc = blockIdx.y;          // 0..31
    const int ic = threadIdx.x & 127;   // input channel
    const int cg = threadIdx.x >> 7;    // column group: 0 -> wi 0..6, 1 -> wi 7..13

    const int hm1 = (h + 13) % 14;      // x row feeding this output row

    // x row: 14 floats; offset ic*196 + hm1*14 even -> 7x LDG.64
    const float2* xr2 = reinterpret_cast<const float2*>(x + ic * 196 + hm1 * 14);
    float xrow[14];
#pragma unroll
    for (int j = 0; j < 7; j++) {
        float2 v = __ldg(xr2 + j);
        xrow[2 * j]     = v.x;
        xrow[2 * j + 1] = v.y;
    }

    // w[oc][k][ic]: contiguous in ic -> coalesced per warp
    const float w0 = __ldg(w + oc * 384 + 0 * 128 + ic);
    const float w1 = __ldg(w + oc * 384 + 1 * 128 + ic);
    const float w2 = __ldg(w + oc * 384 + 2 * 128 + ic);

    float acc[7];
    if (cg == 0) {
        // wi = 0..6
#pragma unroll
        for (int i = 0; i < 7; i++) {
            const int wi = i;
            float a = w1 * xrow[(wi + 13) % 14];
            if (wi >= 1) a += w0 * xrow[(wi + 12) % 14];
            a += w2 * xrow[wi];                       // wi<=6 always valid
            acc[i] = a;
        }
    } else {
        // wi = 7..13
#pragma unroll
        for (int i = 0; i < 7; i++) {
            const int wi = 7 + i;
            float a = w1 * xrow[(wi + 13) % 14];
            a += w0 * xrow[(wi + 12) % 14];           // wi>=7 always valid
            if (wi <= 12) a += w2 * xrow[wi];
            acc[i] = a;
        }
    }

    // Stage 1: pack into smem. colgrp0 -> cols [0..6], colgrp1 -> cols [8..14]
    {
        float* dst = &part[ic][cg * 8];
        reinterpret_cast<float4*>(dst)[0] = make_float4(acc[0], acc[1], acc[2], acc[3]);
        reinterpret_cast<float2*>(dst + 4)[0] = make_float2(acc[4], acc[5]);
        dst[6] = acc[6];
    }
    __syncthreads();

    // Stage 2: 112 threads; thread t = g*14 + wi sums ic in [g*16, g*16+16)
    if (threadIdx.x < 112) {
        const int g   = threadIdx.x / 14;
        const int wi  = threadIdx.x % 14;
        const int col = wi + (wi >= 7 ? 1 : 0);       // skip pad col 7
        const int base = g * 16;
        float v[16];
#pragma unroll
        for (int j = 0; j < 16; j++) v[j] = part[base + j][col];
        float s01 = (v[0] + v[1]) + (v[2] + v[3]);
        float s23 = (v[4] + v[5]) + (v[6] + v[7]);
        float s45 = (v[8] + v[9]) + (v[10] + v[11]);
        float s67 = (v[12] + v[13]) + (v[14] + v[15]);
        part2[g][wi] = (s01 + s23) + (s45 + s67);
    }
    __syncthreads();

    // Stage 3: 14 threads sum the 8 group partials and store
    if (threadIdx.x < 14) {
        const int wi = threadIdx.x;
        float s = ((part2[0][wi] + part2[1][wi]) + (part2[2][wi] + part2[3][wi]))
                + ((part2[4][wi] + part2[5][wi]) + (part2[6][wi] + part2[7][wi]));
        out[oc * 196 + h * 14 + wi] = s;
    }
}

extern "C" void kernel_launch(void* const* d_in, const int* in_sizes, int n_in,
                              void* d_out, int out_size) {
    const float* x = (const float*)d_in[0];   // (1,128,14,14) = 25088 floats
    const float* w = (const float*)d_in[1];   // (32,3,128)    = 12288 floats
    float* out = (float*)d_out;               // (1,32,14,14)  = 6272 floats

    dim3 grid(14, 32);
    rolled_conv_kernel<<<grid, 256>>>(x, w, out);
}